// round 1
// baseline (speedup 1.0000x reference)
#include <cuda_runtime.h>
#include <cuda_bf16.h>

// Problem constants
// x:     [1024, 4096]  fp32
// core0: [1, 16, 16, 32]   (i1, j1, r1)
// core1: [32, 16, 16, 32]  (r1, i2, j2, r2)
// core2: [32, 16, 16, 1]   (r2, i3, j3)
// bias:  [4096]
// y[b, i1*256+i2*16+i3] = sum_j W[i,j] x[b,j] + bias[i]
// W[i,j] = sum_{r1,r2} core0[i1,j1,r1] core1[r1,i2,j2,r2] core2[r2,i3,j3]

#define KDIM 4096
#define MDIM 1024
#define NDIM 4096

// Scratch: allowed as __device__ globals (no cudaMalloc permitted).
__device__ float g_T01[256 * 256 * 32];   // [i1i2][j1j2][r2]  (8 MB)
__device__ float g_W[4096 * 4096];        // [i][j]            (64 MB)

// ---------------------------------------------------------------------------
// Kernel 1: T01[i1i2, j1j2, r2] = sum_r1 core0[i1,j1,r1] * core1[r1,i2,j2,r2]
// 2,097,152 elements, 32 FMAs each.
// ---------------------------------------------------------------------------
__global__ void build_t01_kernel(const float* __restrict__ c0,
                                 const float* __restrict__ c1) {
    int idx = blockIdx.x * blockDim.x + threadIdx.x;
    if (idx >= 256 * 256 * 32) return;
    int r2 = idx & 31;
    int jj = (idx >> 5) & 255;   // j1*16 + j2
    int ii = idx >> 13;          // i1*16 + i2
    int j1 = jj >> 4, j2 = jj & 15;
    int i1 = ii >> 4, i2 = ii & 15;

    const float* a = c0 + (i1 * 16 + j1) * 32;          // over r1, stride 1
    const float* b = c1 + i2 * 512 + j2 * 32 + r2;      // over r1, stride 8192

    float s = 0.f;
#pragma unroll
    for (int r1 = 0; r1 < 32; ++r1)
        s += a[r1] * b[r1 * 8192];
    g_T01[idx] = s;
}

// ---------------------------------------------------------------------------
// Kernel 2: W[i, j] = sum_r2 T01[ihi, jhi, r2] * core2[r2, i3, j3]
// Memory-bound on the 64 MB write; T01 rows and core2 are cache-resident.
// ---------------------------------------------------------------------------
__global__ void build_w_kernel(const float* __restrict__ c2) {
    int j = blockIdx.x * blockDim.x + threadIdx.x;   // 0..4095
    int i = blockIdx.y;                              // 0..4095
    int ihi = i >> 4, i3 = i & 15;
    int jhi = j >> 4, j3 = j & 15;

    const float* t = g_T01 + (ihi * 256 + jhi) * 32;     // over r2, stride 1
    const float* c = c2 + i3 * 16 + j3;                  // over r2, stride 256

    float s = 0.f;
#pragma unroll
    for (int r = 0; r < 32; ++r)
        s += t[r] * c[r * 256];
    g_W[i * 4096 + j] = s;
}

// ---------------------------------------------------------------------------
// Kernel 3: GEMM  C[M,N] = A[M,K] * W[N,K]^T + bias
// 128x128 tile, BK=16, 256 threads, 8x8 per thread, double-buffered smem.
// Both operands are K-contiguous ("TN" dot-product layout) -> transpose into
// smem on load. 256 blocks = 1 full wave at 2 CTAs/SM.
// ---------------------------------------------------------------------------
#define BM 128
#define BN 128
#define BK 16

__global__ __launch_bounds__(256, 2)
void gemm_kernel(const float* __restrict__ A,
                 const float* __restrict__ bias,
                 float* __restrict__ C) {
    __shared__ __align__(16) float As[2][BK][BM + 4];
    __shared__ __align__(16) float Bs[2][BK][BN + 4];

    const int K = KDIM;
    const int tid = threadIdx.x;
    const int bm = blockIdx.y * BM;
    const int bn = blockIdx.x * BN;

    // loader mapping: each thread loads 2 float4 from A and 2 from B per tile
    const int lrow = tid >> 2;            // 0..63
    const int lk   = (tid & 3) << 2;      // 0,4,8,12

    // compute mapping: columns tx*4 & tx*4+64, rows ty*4 & ty*4+64
    const int tx = tid & 15;
    const int ty = tid >> 4;

    const float* Ag = A   + (size_t)(bm + lrow) * K + lk;
    const float* Bg = g_W + (size_t)(bn + lrow) * K + lk;

    float acc[8][8];
#pragma unroll
    for (int i = 0; i < 8; ++i)
#pragma unroll
        for (int j = 0; j < 8; ++j) acc[i][j] = 0.f;

    // preload tile 0
#pragma unroll
    for (int r = 0; r < 2; ++r) {
        float4 av = *(const float4*)(Ag + (size_t)r * 64 * K);
        float4 bv = *(const float4*)(Bg + (size_t)r * 64 * K);
        int row = lrow + r * 64;
        As[0][lk + 0][row] = av.x; As[0][lk + 1][row] = av.y;
        As[0][lk + 2][row] = av.z; As[0][lk + 3][row] = av.w;
        Bs[0][lk + 0][row] = bv.x; Bs[0][lk + 1][row] = bv.y;
        Bs[0][lk + 2][row] = bv.z; Bs[0][lk + 3][row] = bv.w;
    }
    __syncthreads();

    int buf = 0;
    for (int kt = 0; kt < K; kt += BK) {
        float4 ra[2], rb[2];
        const bool nxt = (kt + BK) < K;
        if (nxt) {
#pragma unroll
            for (int r = 0; r < 2; ++r) {
                ra[r] = *(const float4*)(Ag + (size_t)r * 64 * K + kt + BK);
                rb[r] = *(const float4*)(Bg + (size_t)r * 64 * K + kt + BK);
            }
        }

#pragma unroll
        for (int k = 0; k < BK; ++k) {
            float4 a0 = *(const float4*)&As[buf][k][ty * 4];
            float4 a1 = *(const float4*)&As[buf][k][ty * 4 + 64];
            float4 b0 = *(const float4*)&Bs[buf][k][tx * 4];
            float4 b1 = *(const float4*)&Bs[buf][k][tx * 4 + 64];
            float a[8] = {a0.x, a0.y, a0.z, a0.w, a1.x, a1.y, a1.z, a1.w};
            float b[8] = {b0.x, b0.y, b0.z, b0.w, b1.x, b1.y, b1.z, b1.w};
#pragma unroll
            for (int i = 0; i < 8; ++i)
#pragma unroll
                for (int j = 0; j < 8; ++j)
                    acc[i][j] += a[i] * b[j];
        }

        if (nxt) {
#pragma unroll
            for (int r = 0; r < 2; ++r) {
                int row = lrow + r * 64;
                As[buf ^ 1][lk + 0][row] = ra[r].x; As[buf ^ 1][lk + 1][row] = ra[r].y;
                As[buf ^ 1][lk + 2][row] = ra[r].z; As[buf ^ 1][lk + 3][row] = ra[r].w;
                Bs[buf ^ 1][lk + 0][row] = rb[r].x; Bs[buf ^ 1][lk + 1][row] = rb[r].y;
                Bs[buf ^ 1][lk + 2][row] = rb[r].z; Bs[buf ^ 1][lk + 3][row] = rb[r].w;
            }
            __syncthreads();
            buf ^= 1;
        }
    }

    // epilogue: add bias, store
    float bc0[4], bc1[4];
#pragma unroll
    for (int c = 0; c < 4; ++c) {
        bc0[c] = bias[bn + tx * 4 + c];
        bc1[c] = bias[bn + tx * 4 + 64 + c];
    }
#pragma unroll
    for (int ii = 0; ii < 8; ++ii) {
        int m = bm + ty * 4 + ((ii < 4) ? ii : (60 + ii));  // ii>=4 -> +64+(ii-4)
        float4 o0 = make_float4(acc[ii][0] + bc0[0], acc[ii][1] + bc0[1],
                                acc[ii][2] + bc0[2], acc[ii][3] + bc0[3]);
        float4 o1 = make_float4(acc[ii][4] + bc1[0], acc[ii][5] + bc1[1],
                                acc[ii][6] + bc1[2], acc[ii][7] + bc1[3]);
        *(float4*)&C[(size_t)m * NDIM + bn + tx * 4]      = o0;
        *(float4*)&C[(size_t)m * NDIM + bn + tx * 4 + 64] = o1;
    }
}

// ---------------------------------------------------------------------------
extern "C" void kernel_launch(void* const* d_in, const int* in_sizes, int n_in,
                              void* d_out, int out_size) {
    const float* x     = (const float*)d_in[0];
    const float* core0 = (const float*)d_in[1];
    const float* core1 = (const float*)d_in[2];
    const float* core2 = (const float*)d_in[3];
    const float* bias  = (const float*)d_in[4];
    float* out = (float*)d_out;

    // 1) merge core0+core1 -> T01   (2M elems)
    build_t01_kernel<<<(256 * 256 * 32) / 256, 256>>>(core0, core1);

    // 2) merge T01+core2 -> dense W[4096,4096]
    build_w_kernel<<<dim3(NDIM / 256, NDIM), 256>>>(core2);

    // 3) Y = X * W^T + bias
    gemm_kernel<<<dim3(NDIM / BN, MDIM / BM), 256>>>(x, bias, out);
}

// round 3
// speedup vs baseline: 1.9823x; 1.9823x over previous
#include <cuda_runtime.h>
#include <cuda_bf16.h>
#include <cstdint>

// ===========================================================================
// TrainableMPOLayer: y = X @ W^T + bias, W = dense collapse of 3-core MPO.
//   1) T01 = core0 x core1
//   2) Whi/Wlo bf16 = split(T01 x core2)
//   3) Xhi/Xlo bf16 = split(x)
//   4) Y = Xhi*Whi + Xhi*Wlo + Xlo*Whi + bias   via mma.sync bf16 (HMMA)
// (tcgen05 is unavailable: harness compiles through compute_103 virtual arch,
//  which rejects sm_103a-specific PTX. mma.sync.m16n8k16 is the legal tensor
//  path.)
// ===========================================================================

#define KDIM 4096
#define MDIM 1024
#define NDIM 4096

__device__ float          g_T01[256 * 256 * 32];        // 8 MB
__device__ __nv_bfloat16  g_Whi[(size_t)4096 * 4096];   // 32 MB
__device__ __nv_bfloat16  g_Wlo[(size_t)4096 * 4096];   // 32 MB
__device__ __nv_bfloat16  g_Xhi[(size_t)1024 * 4096];   // 8 MB
__device__ __nv_bfloat16  g_Xlo[(size_t)1024 * 4096];   // 8 MB

// ---------------------------------------------------------------------------
// helpers
// ---------------------------------------------------------------------------
__device__ __forceinline__ uint32_t smem_u32(const void* p) {
    uint32_t a;
    asm("{ .reg .u64 t; cvta.to.shared.u64 t, %1; cvt.u32.u64 %0, t; }"
        : "=r"(a) : "l"(p));
    return a;
}

__device__ __forceinline__ void cpasync16(uint32_t dst, const void* src) {
    asm volatile("cp.async.cg.shared.global [%0], [%1], 16;"
                 :: "r"(dst), "l"(src) : "memory");
}

__device__ __forceinline__ void ldsm4(uint32_t& r0, uint32_t& r1,
                                      uint32_t& r2, uint32_t& r3, uint32_t a) {
    asm volatile("ldmatrix.sync.aligned.m8n8.x4.shared.b16 {%0,%1,%2,%3}, [%4];"
                 : "=r"(r0), "=r"(r1), "=r"(r2), "=r"(r3) : "r"(a));
}

__device__ __forceinline__ void mma16816(float* d, const uint32_t* a,
                                         uint32_t b0, uint32_t b1) {
    asm volatile(
        "mma.sync.aligned.m16n8k16.row.col.f32.bf16.bf16.f32 "
        "{%0,%1,%2,%3}, {%4,%5,%6,%7}, {%8,%9}, {%0,%1,%2,%3};"
        : "+f"(d[0]), "+f"(d[1]), "+f"(d[2]), "+f"(d[3])
        : "r"(a[0]), "r"(a[1]), "r"(a[2]), "r"(a[3]), "r"(b0), "r"(b1));
}

// ---------------------------------------------------------------------------
// Kernel 1: T01[ii, jj, r2] = sum_r1 core0[i1,j1,r1] * core1[r1,i2,j2,r2]
// ---------------------------------------------------------------------------
__global__ void build_t01_kernel(const float* __restrict__ c0,
                                 const float* __restrict__ c1) {
    int idx = blockIdx.x * blockDim.x + threadIdx.x;   // 0 .. 256*256*8-1
    int r2q = idx & 7;
    int jj  = (idx >> 3) & 255;
    int ii  = idx >> 11;
    int j1 = jj >> 4, j2 = jj & 15;
    int i1 = ii >> 4, i2 = ii & 15;

    const float*  a = c0 + (i1 * 16 + j1) * 32;
    const float4* b = (const float4*)(c1 + i2 * 512 + j2 * 32 + r2q * 4);

    float4 s = make_float4(0.f, 0.f, 0.f, 0.f);
#pragma unroll
    for (int r1 = 0; r1 < 32; ++r1) {
        float  av = a[r1];
        float4 bv = b[(size_t)r1 * 2048];
        s.x += av * bv.x; s.y += av * bv.y; s.z += av * bv.z; s.w += av * bv.w;
    }
    *(float4*)(g_T01 + (size_t)idx * 4) = s;
}

// ---------------------------------------------------------------------------
// Kernel 2: W[i,j] = sum_r2 T01[ihi,jhi,r2] * core2[r2,i3,j3] -> bf16 hi/lo
// ---------------------------------------------------------------------------
__global__ void build_w_kernel(const float* __restrict__ c2) {
    int j = blockIdx.x * blockDim.x + threadIdx.x;
    int i = blockIdx.y;
    int ihi = i >> 4, i3 = i & 15;
    int jhi = j >> 4, j3 = j & 15;

    const float4* t = (const float4*)(g_T01 + ((size_t)ihi * 256 + jhi) * 32);
    const float*  c = c2 + i3 * 16 + j3;

    float s = 0.f;
#pragma unroll
    for (int r4 = 0; r4 < 8; ++r4) {
        float4 tv = t[r4];
        s += tv.x * c[(r4 * 4 + 0) * 256];
        s += tv.y * c[(r4 * 4 + 1) * 256];
        s += tv.z * c[(r4 * 4 + 2) * 256];
        s += tv.w * c[(r4 * 4 + 3) * 256];
    }
    __nv_bfloat16 hi = __float2bfloat16(s);
    float lo = s - __bfloat162float(hi);
    size_t o = (size_t)i * 4096 + j;
    g_Whi[o] = hi;
    g_Wlo[o] = __float2bfloat16(lo);
}

// ---------------------------------------------------------------------------
// Kernel 3: split X into bf16 hi/lo
// ---------------------------------------------------------------------------
__global__ void split_x_kernel(const float* __restrict__ x) {
    int idx = blockIdx.x * blockDim.x + threadIdx.x;
    float4 v = ((const float4*)x)[idx];
    __nv_bfloat16 h0 = __float2bfloat16(v.x);
    __nv_bfloat16 h1 = __float2bfloat16(v.y);
    __nv_bfloat16 h2 = __float2bfloat16(v.z);
    __nv_bfloat16 h3 = __float2bfloat16(v.w);
    __nv_bfloat16 l0 = __float2bfloat16(v.x - __bfloat162float(h0));
    __nv_bfloat16 l1 = __float2bfloat16(v.y - __bfloat162float(h1));
    __nv_bfloat16 l2 = __float2bfloat16(v.z - __bfloat162float(h2));
    __nv_bfloat16 l3 = __float2bfloat16(v.w - __bfloat162float(h3));
    __nv_bfloat162* Hp = (__nv_bfloat162*)g_Xhi;
    __nv_bfloat162* Lp = (__nv_bfloat162*)g_Xlo;
    Hp[idx * 2 + 0] = __nv_bfloat162(h0, h1);
    Hp[idx * 2 + 1] = __nv_bfloat162(h2, h3);
    Lp[idx * 2 + 0] = __nv_bfloat162(l0, l1);
    Lp[idx * 2 + 1] = __nv_bfloat162(l2, l3);
}

// ---------------------------------------------------------------------------
// Kernel 4: HMMA GEMM. C[1024,4096] = Xsplit @ Wsplit^T + bias
// CTA: 128x128, BK=64 (128 B/row bf16, SW128 swizzle), 2-stage cp.async.
// 8 warps as 4(M) x 2(N); warp tile 32x64; mma.sync m16n8k16 bf16->fp32.
// 3 MMA terms: Ahi*Bhi + Ahi*Blo + Alo*Bhi.
// ---------------------------------------------------------------------------
#define GBM 128
#define GBN 128
#define GBK 64
#define NKT (KDIM / GBK)            // 64
#define ST_AHI 0
#define ST_ALO 16384
#define ST_BHI 32768
#define ST_BLO 49152
#define STAGE_BYTES 65536
#define SMEM_TOTAL (2 * STAGE_BYTES)   // 128 KB

__device__ __forceinline__ void load_stage(uint32_t st, int bm, int bn,
                                           int kt, int tid) {
    const size_t krow = (size_t)kt * 128;     // byte offset within K row
#pragma unroll
    for (int c = tid; c < 1024; c += 256) {   // 128 rows x 8 16B-chunks
        int row = c >> 3, ch = c & 7;
        uint32_t so = (uint32_t)(row * 128 + ch * 16);
        so ^= (so >> 3) & 0x70;
        const size_t ga = (size_t)(bm + row) * 8192 + krow + ch * 16;
        const size_t gb = (size_t)(bn + row) * 8192 + krow + ch * 16;
        cpasync16(st + ST_AHI + so, (const char*)g_Xhi + ga);
        cpasync16(st + ST_ALO + so, (const char*)g_Xlo + ga);
        cpasync16(st + ST_BHI + so, (const char*)g_Whi + gb);
        cpasync16(st + ST_BLO + so, (const char*)g_Wlo + gb);
    }
}

__global__ __launch_bounds__(256, 1)
void gemm_mma_kernel(const float* __restrict__ bias, float* __restrict__ C) {
    extern __shared__ __align__(1024) char smem[];
    const uint32_t sbase = smem_u32(smem);
    const int tid  = threadIdx.x;
    const int wid  = tid >> 5;
    const int lane = tid & 31;
    const int wm = wid & 3;          // 4 M-warps (32 rows each)
    const int wn = wid >> 2;         // 2 N-warps (64 cols each)
    const int bm = blockIdx.y * GBM;
    const int bn = blockIdx.x * GBN;

    // ldmatrix per-lane addressing (row = lane&15, 16B chunk = lane>>4)
    const int lrow   = lane & 15;
    const int lchunk = (lane >> 4) * 16;

    // A tiles: rows wm*32 + mt*16 + lrow
    uint32_t a_base[2];   // byte base of row (no col)
    uint32_t a_mask[2];   // swizzle XOR mask for this row
#pragma unroll
    for (int mt = 0; mt < 2; ++mt) {
        int r = wm * 32 + mt * 16 + lrow;
        a_base[mt] = (uint32_t)(r * 128);
        a_mask[mt] = (uint32_t)((r & 7) << 4);
    }
    // B n16-chunks: rows wn*64 + c*16 + lrow
    uint32_t b_base[4], b_mask[4];
#pragma unroll
    for (int c = 0; c < 4; ++c) {
        int r = wn * 64 + c * 16 + lrow;
        b_base[c] = (uint32_t)(r * 128);
        b_mask[c] = (uint32_t)((r & 7) << 4);
    }

    float acc[2][8][4];
#pragma unroll
    for (int mt = 0; mt < 2; ++mt)
#pragma unroll
        for (int nt = 0; nt < 8; ++nt)
#pragma unroll
            for (int e = 0; e < 4; ++e) acc[mt][nt][e] = 0.f;

    load_stage(sbase, bm, bn, 0, tid);
    asm volatile("cp.async.commit_group;" ::: "memory");

    int buf = 0;
    for (int kt = 0; kt < NKT; ++kt) {
        if (kt + 1 < NKT) {
            load_stage(sbase + (buf ^ 1) * STAGE_BYTES, bm, bn, kt + 1, tid);
            asm volatile("cp.async.commit_group;" ::: "memory");
            asm volatile("cp.async.wait_group 1;" ::: "memory");
        } else {
            asm volatile("cp.async.wait_group 0;" ::: "memory");
        }
        __syncthreads();

        const uint32_t st = sbase + buf * STAGE_BYTES;
#pragma unroll
        for (int ks = 0; ks < 4; ++ks) {
            const uint32_t kb = (uint32_t)(ks * 32);
            uint32_t ah[2][4], al[2][4];
#pragma unroll
            for (int mt = 0; mt < 2; ++mt) {
                uint32_t col = (uint32_t)(lchunk + ks * 32);  // careful: per-k chunk
                col = (lchunk + kb) ^ a_mask[mt];
                ldsm4(ah[mt][0], ah[mt][1], ah[mt][2], ah[mt][3],
                      st + ST_AHI + a_base[mt] + col);
                ldsm4(al[mt][0], al[mt][1], al[mt][2], al[mt][3],
                      st + ST_ALO + a_base[mt] + col);
            }
            uint32_t bh[4][4], bl[4][4];
#pragma unroll
            for (int c = 0; c < 4; ++c) {
                uint32_t col = (lchunk + kb) ^ b_mask[c];
                ldsm4(bh[c][0], bh[c][1], bh[c][2], bh[c][3],
                      st + ST_BHI + b_base[c] + col);
                ldsm4(bl[c][0], bl[c][1], bl[c][2], bl[c][3],
                      st + ST_BLO + b_base[c] + col);
            }
#pragma unroll
            for (int mt = 0; mt < 2; ++mt)
#pragma unroll
                for (int nt = 0; nt < 8; ++nt) {
                    const int c = nt >> 1, o = nt & 1;   // frag regs {o, o+2}
                    mma16816(acc[mt][nt], ah[mt], bh[c][o], bh[c][o + 2]);
                    mma16816(acc[mt][nt], ah[mt], bl[c][o], bl[c][o + 2]);
                    mma16816(acc[mt][nt], al[mt], bh[c][o], bh[c][o + 2]);
                }
        }
        __syncthreads();
        buf ^= 1;
    }

    // epilogue: acc -> C + bias. m16n8 frag: row = lane>>2 (+8), col = (lane&3)*2
    const int gq = lane >> 2, rq = lane & 3;
#pragma unroll
    for (int mt = 0; mt < 2; ++mt) {
        const int r0 = bm + wm * 32 + mt * 16 + gq;
#pragma unroll
        for (int nt = 0; nt < 8; ++nt) {
            const int col = bn + wn * 64 + nt * 8 + rq * 2;
            float2 bv = *(const float2*)&bias[col];
            float2 o0 = make_float2(acc[mt][nt][0] + bv.x, acc[mt][nt][1] + bv.y);
            float2 o1 = make_float2(acc[mt][nt][2] + bv.x, acc[mt][nt][3] + bv.y);
            *(float2*)&C[(size_t)r0 * NDIM + col]       = o0;
            *(float2*)&C[(size_t)(r0 + 8) * NDIM + col] = o1;
        }
    }
}

// ---------------------------------------------------------------------------
extern "C" void kernel_launch(void* const* d_in, const int* in_sizes, int n_in,
                              void* d_out, int out_size) {
    const float* x     = (const float*)d_in[0];
    const float* core0 = (const float*)d_in[1];
    const float* core1 = (const float*)d_in[2];
    const float* core2 = (const float*)d_in[3];
    const float* bias  = (const float*)d_in[4];
    float* out = (float*)d_out;

    build_t01_kernel<<<(256 * 256 * 8) / 256, 256>>>(core0, core1);
    build_w_kernel<<<dim3(NDIM / 256, NDIM), 256>>>(core2);
    split_x_kernel<<<(MDIM * KDIM / 4) / 256, 256>>>(x);

    cudaFuncSetAttribute(gemm_mma_kernel,
                         cudaFuncAttributeMaxDynamicSharedMemorySize, SMEM_TOTAL);
    gemm_mma_kernel<<<dim3(NDIM / GBN, MDIM / GBM), 256, SMEM_TOTAL>>>(bias, out);
}